// round 3
// baseline (speedup 1.0000x reference)
#include <cuda_runtime.h>
#include <cuda_bf16.h>
#include <stdint.h>

// ---------------------------------------------------------------------------
// LennardJones: per-edge LJ energy + scatter-add of analytic forces to nodes.
// Outputs (flattened, concatenated):
//   d_out[0]              = potential_energy = 0.5 * sum_e pe_e
//   d_out[1 .. 1+3N)      = forces          = -0.5 * analytic   (exact identity)
//   d_out[1+3N .. 1+6N)   = analytic_force  = segsum(f_scalar * bv)
// ---------------------------------------------------------------------------

#define SCRATCH_CAP 131072  // >= n_nodes (100000); padded float4 accumulator

__device__ float4 g_acc[SCRATCH_CAP];  // per-node {fx,fy,fz,pad}
__device__ double g_pe;                // sum of pe over all edges

// e0 = 4*((1/3)^12 - (1/3)^6), computed in double, rounded to float (matches ref)
__device__ __constant__ const float E0C =
    (float)(4.0 * (1.8816764231589208e-06 - 1.3717421124828533e-03));

// ---------------------------------------------------------------------------

__global__ void zero_kernel(float* __restrict__ out_acc, int n_pad, int n_direct) {
    int i = blockIdx.x * blockDim.x + threadIdx.x;
    if (i == 0) g_pe = 0.0;
    if (i < n_pad) g_acc[i] = make_float4(0.f, 0.f, 0.f, 0.f);
    if (i < n_direct) out_acc[i] = 0.f;  // fallback path only (n_direct==0 normally)
}

// One edge: compute pe contribution, scatter analytic force.
__device__ __forceinline__ float edge_op_pad(float x, float y, float z, int n) {
    float r2  = fmaf(x, x, fmaf(y, y, z * z));
    float inv = 1.0f / r2;
    float c6  = inv * inv * inv;
    float c12 = c6 * c6;
    float fs  = -24.0f * (2.0f * c12 - c6) * inv;
    float4* p = &g_acc[n];
    asm volatile("red.global.add.v4.f32 [%0], {%1,%2,%3,%4};"
                 :: "l"(p), "f"(fs * x), "f"(fs * y), "f"(fs * z), "f"(0.0f)
                 : "memory");
    return 4.0f * (c12 - c6) - E0C;
}

__device__ __forceinline__ float edge_op_direct(float x, float y, float z, int n,
                                                float* __restrict__ acc) {
    float r2  = fmaf(x, x, fmaf(y, y, z * z));
    float inv = 1.0f / r2;
    float c6  = inv * inv * inv;
    float c12 = c6 * c6;
    float fs  = -24.0f * (2.0f * c12 - c6) * inv;
    atomicAdd(acc + 3 * n + 0, fs * x);
    atomicAdd(acc + 3 * n + 1, fs * y);
    atomicAdd(acc + 3 * n + 2, fs * z);
    return 4.0f * (c12 - c6) - E0C;
}

template <bool PAD>
__global__ void lj_main_kernel(const float* __restrict__ bv,
                               const int* __restrict__ dst,
                               float* __restrict__ acc_direct, int E) {
    int t  = blockIdx.x * blockDim.x + threadIdx.x;
    int e0 = t * 4;
    float pe = 0.0f;

    if (e0 + 3 < E) {
        // 4 edges: 3x LDG.128 for coords (48B, 16B-aligned), 1x LDG.128 for dst
        const float4* bv4  = reinterpret_cast<const float4*>(bv);
        const int4*   dst4 = reinterpret_cast<const int4*>(dst);
        float4 a = bv4[3 * t + 0];
        float4 b = bv4[3 * t + 1];
        float4 c = bv4[3 * t + 2];
        int4   d = dst4[t];
        if (PAD) {
            pe += edge_op_pad(a.x, a.y, a.z, d.x);
            pe += edge_op_pad(a.w, b.x, b.y, d.y);
            pe += edge_op_pad(b.z, b.w, c.x, d.z);
            pe += edge_op_pad(c.y, c.z, c.w, d.w);
        } else {
            pe += edge_op_direct(a.x, a.y, a.z, d.x, acc_direct);
            pe += edge_op_direct(a.w, b.x, b.y, d.y, acc_direct);
            pe += edge_op_direct(b.z, b.w, c.x, d.z, acc_direct);
            pe += edge_op_direct(c.y, c.z, c.w, d.w, acc_direct);
        }
    } else {
        for (int e = e0; e < E; e++) {
            float x = bv[3 * e + 0], y = bv[3 * e + 1], z = bv[3 * e + 2];
            int n = dst[e];
            if (PAD) pe += edge_op_pad(x, y, z, n);
            else     pe += edge_op_direct(x, y, z, n, acc_direct);
        }
    }

    // block-level PE reduction -> one double atomic per block
    __shared__ float sred[8];
    unsigned lane = threadIdx.x & 31u;
    unsigned warp = threadIdx.x >> 5;
    #pragma unroll
    for (int off = 16; off > 0; off >>= 1)
        pe += __shfl_down_sync(0xFFFFFFFFu, pe, off);
    if (lane == 0) sred[warp] = pe;
    __syncthreads();
    if (warp == 0) {
        float v = (lane < (blockDim.x >> 5)) ? sred[lane] : 0.0f;
        #pragma unroll
        for (int off = 4; off > 0; off >>= 1)
            v += __shfl_down_sync(0xFFFFFFFFu, v, off);
        if (lane == 0) atomicAdd(&g_pe, (double)v);
    }
}

template <bool PAD>
__global__ void finalize_kernel(float* __restrict__ out, int N) {
    int i = blockIdx.x * blockDim.x + threadIdx.x;
    int total = 3 * N;
    if (i < total) {
        float a;
        if (PAD) {
            int node = i / 3;
            int comp = i - 3 * node;
            a = reinterpret_cast<const float*>(g_acc)[node * 4 + comp];
        } else {
            a = out[1 + total + i];  // already accumulated in place
        }
        out[1 + i]         = -0.5f * a;  // autograd forces
        out[1 + total + i] = a;          // analytic forces
    }
    if (i == 0) out[0] = (float)(0.5 * g_pe);
}

// ---------------------------------------------------------------------------

extern "C" void kernel_launch(void* const* d_in, const int* in_sizes, int n_in,
                              void* d_out, int out_size) {
    const float* bv  = (const float*)d_in[0];
    const int*   dst = (const int*)d_in[1];
    float* out = (float*)d_out;

    int E = in_sizes[1];
    int N = (out_size - 1) / 6;

    bool pad = (N <= SCRATCH_CAP);
    float* acc_direct = out + 1 + 3 * N;  // analytic-force region (fallback path)

    // 1) zero accumulators
    {
        int n_pad    = pad ? N : 0;
        int n_direct = pad ? 0 : 3 * N;
        int nz = n_pad > n_direct ? n_pad : n_direct;
        if (nz < 1) nz = 1;
        int threads = 256, blocks = (nz + threads - 1) / threads;
        zero_kernel<<<blocks, threads>>>(acc_direct, n_pad, n_direct);
    }

    // 2) main edge kernel: 4 edges per thread
    {
        int threads = 256;
        int nthreads_needed = (E + 3) / 4;
        int blocks = (nthreads_needed + threads - 1) / threads;
        if (pad)
            lj_main_kernel<true><<<blocks, threads>>>(bv, dst, acc_direct, E);
        else
            lj_main_kernel<false><<<blocks, threads>>>(bv, dst, acc_direct, E);
    }

    // 3) finalize: write PE, forces, analytic forces
    {
        int threads = 256;
        int blocks = (3 * N + threads - 1) / threads;
        if (pad)
            finalize_kernel<true><<<blocks, threads>>>(out, N);
        else
            finalize_kernel<false><<<blocks, threads>>>(out, N);
    }
}